// round 11
// baseline (speedup 1.0000x reference)
#include <cuda_runtime.h>
#include <cuda_bf16.h>
#include <math.h>
#include <stdint.h>

// ---------------- problem constants ----------------
#define C_CH   256
#define TOPK   1000

__device__ __constant__ float c_ws[2][3] = {
    {90.50966799187809f, 64.0f, 45.254833995939045f},
    {181.01933598375618f, 128.0f, 90.50966799187809f}};
__device__ __constant__ float c_hs[2][3] = {
    {45.254833995939045f, 64.0f, 90.50966799187809f},
    {90.50966799187809f, 128.0f, 181.01933598375618f}};

// ---------------- device scratch (static, no allocs) ----------------
__device__ float  g_part0[3 * 4096 * C_CH];      // level0 conv partials (per tap-row group)
__device__ float  g_part1[3 * 1024 * C_CH];      // level1 conv partials
__device__ float  g_wtd[9 * C_CH * 2 * C_CH];    // transposed weights, co-DUPLICATED pairs
__device__ float4 g_boxes0[4 * 3072];
__device__ float4 g_boxes1[4 * 768];
__device__ float  g_scores0[4 * 3072];
__device__ float  g_scores1[4 * 768];
__device__ float4 g_sboxes[8 * 3072];            // per-task sorted boxes
__device__ float  g_sscores[8 * 3072];           // per-task sorted scores
__device__ float  g_sarea[8 * 3072];             // per-task sorted box areas
__device__ unsigned g_mask[8u * 3072u * 96u];    // IoU>thresh bitmask, row-major per task
__device__ float4 g_kb[8 * TOPK];                // kept boxes per task
__device__ float  g_ks[8 * TOPK];                // kept scores per task

// ---------------- small PTX helpers ----------------
__device__ __forceinline__ void fma2(unsigned long long& d, unsigned long long a,
                                     unsigned long long b)
{
    asm("fma.rn.f32x2 %0, %1, %2, %0;" : "+l"(d) : "l"(a), "l"(b));
}
__device__ __forceinline__ void cp_async16(uint32_t dst, const void* src)
{
    asm volatile("cp.async.cg.shared.global [%0], [%1], 16;" :: "r"(dst), "l"(src));
}
__device__ __forceinline__ void cp_async4(uint32_t dst, const void* src, bool ok)
{
    int sz = ok ? 4 : 0;
    asm volatile("cp.async.ca.shared.global [%0], [%1], 4, %2;" :: "r"(dst), "l"(src), "r"(sz));
}

// ---------------- weight transpose + duplicate ----------------
// g_wtd[tap][ci][2*co] = g_wtd[tap][ci][2*co+1] = w[co][ci][tap]
__global__ void wtrans_kernel(const float* __restrict__ w)
{
    int idx = blockIdx.x * blockDim.x + threadIdx.x;
    if (idx >= C_CH * C_CH * 9) return;
    int co  = idx / (C_CH * 9);
    int r   = idx % (C_CH * 9);
    int ci  = r / 9;
    int tap = r % 9;
    float v = w[idx];
    float* dst = g_wtd + ((size_t)tap * C_CH + ci) * (2 * C_CH) + 2 * co;
    dst[0] = v;
    dst[1] = v;
}

// ---------------- 3x3 conv, split-K over tap rows, f32x2 packed FMA ----------------
// 64co x 128pos tile, 128 threads, 8co x 8pos per thread (4 packed pos-pairs).
// As holds co-duplicated weight pairs: the packed (w,w) operand comes straight
// from LDS.128 — no per-kk duplication MOVs. Values/order identical to before.
template <int H, int W, int LEVEL>
__global__ void __launch_bounds__(128, 4) conv3x3_kernel(const float* __restrict__ xin)
{
    constexpr int HW = H * W;
    constexpr int NSLICE = 48;   // 3 taps x 16-deep ci slices
    float* __restrict__ outp = ((LEVEL == 0) ? g_part0 : g_part1)
                               + (size_t)blockIdx.z * (4 * HW * C_CH);

    const int tid  = threadIdx.x;
    const int n0   = blockIdx.x * 128;  // 128 | HW, never crosses image
    const int co0  = blockIdx.y * 64;
    const int b    = n0 / HW;
    const int p0   = n0 % HW;
    const int cth  = tid & 7;           // 8 co-groups of 8
    const int pth  = tid >> 3;          // 16 pos-groups of 8
    const int tap0 = blockIdx.z * 3;
    const float* __restrict__ xb = xin + (size_t)b * C_CH * HW;

    __shared__ float As[3][16][128];    // duplicated weight pairs
    __shared__ float Bs[3][16][128];
    uint32_t sA = (uint32_t)__cvta_generic_to_shared(&As[0][0][0]);
    uint32_t sB = (uint32_t)__cvta_generic_to_shared(&Bs[0][0][0]);

    const int p  = p0 + tid;
    const int py = p / W, px = p % W;

    unsigned long long acc[8][4];
#pragma unroll
    for (int i = 0; i < 8; ++i)
#pragma unroll
        for (int j = 0; j < 4; ++j) acc[i][j] = 0ull;

#define ISSUE_SLICE(s)                                                           \
    {                                                                            \
        int buf = (s) % 3;                                                       \
        int tap = tap0 + ((s) >> 4);                                             \
        int ci0 = ((s) & 15) << 4;                                               \
        int dy = tap / 3 - 1, dx = tap % 3 - 1;                                  \
        const float* wbase = g_wtd + ((size_t)tap * C_CH + ci0) * (2 * C_CH)     \
                             + 2 * co0;                                          \
        _Pragma("unroll")                                                        \
        for (int r = 0; r < 4; ++r) {                                            \
            int f4 = tid + 128 * r;                                              \
            int kk = f4 >> 5, c4 = f4 & 31;                                      \
            cp_async16(sA + buf * (16*128*4) + (kk * 128 + c4 * 4) * 4,          \
                       wbase + (size_t)kk * (2 * C_CH) + c4 * 4);                \
        }                                                                        \
        int ys = py + dy, xs = px + dx;                                          \
        bool ok = ((unsigned)ys < (unsigned)H) && ((unsigned)xs < (unsigned)W);  \
        const float* bsrc = xb + (size_t)ci0 * HW + (ys * W + xs);               \
        _Pragma("unroll")                                                        \
        for (int r = 0; r < 16; ++r)                                             \
            cp_async4(sB + buf * (16*128*4) + (r * 128 + tid) * 4,               \
                      bsrc + (size_t)r * HW, ok);                                \
        asm volatile("cp.async.commit_group;");                                  \
    }

    ISSUE_SLICE(0);
    ISSUE_SLICE(1);

    for (int s = 0; s < NSLICE; ++s) {
        if (s + 2 < NSLICE) {
            asm volatile("cp.async.wait_group 1;");   // slice s arrived
            __syncthreads();                          // publish s; frees buf (s-1)%3
            ISSUE_SLICE(s + 2);                       // writes buf (s+2)%3 == (s-1)%3
        } else {
            asm volatile("cp.async.wait_group %0;" :: "n"(0) : "memory");
            __syncthreads();
        }
        const float (*Ab)[128] = As[s % 3];
        const float (*Bb)[128] = Bs[s % 3];
#pragma unroll
        for (int kk = 0; kk < 16; ++kk) {
            ulonglong2 aA = *(const ulonglong2*)&Ab[kk][cth * 16];
            ulonglong2 aB = *(const ulonglong2*)&Ab[kk][cth * 16 + 4];
            ulonglong2 aC = *(const ulonglong2*)&Ab[kk][cth * 16 + 8];
            ulonglong2 aD = *(const ulonglong2*)&Ab[kk][cth * 16 + 12];
            ulonglong2 bl0 = *(const ulonglong2*)&Bb[kk][pth * 8];
            ulonglong2 bl1 = *(const ulonglong2*)&Bb[kk][pth * 8 + 4];
            unsigned long long ad[8] = {aA.x, aA.y, aB.x, aB.y, aC.x, aC.y, aD.x, aD.y};
            unsigned long long bb[4] = {bl0.x, bl0.y, bl1.x, bl1.y};
#pragma unroll
            for (int i = 0; i < 8; ++i)
#pragma unroll
                for (int j = 0; j < 4; ++j) fma2(acc[i][j], ad[i], bb[j]);
        }
    }
#undef ISSUE_SLICE

#pragma unroll
    for (int j = 0; j < 4; ++j)
#pragma unroll
        for (int h = 0; h < 2; ++h) {
            int n = n0 + pth * 8 + j * 2 + h;
            float v[8];
#pragma unroll
            for (int i = 0; i < 8; ++i) {
                float2 f = *reinterpret_cast<float2*>(&acc[i][j]);
                v[i] = h ? f.y : f.x;
            }
            *(float4*)&outp[(size_t)n * C_CH + co0 + cth * 8] =
                make_float4(v[0], v[1], v[2], v[3]);
            *(float4*)&outp[(size_t)n * C_CH + co0 + cth * 8 + 4] =
                make_float4(v[4], v[5], v[6], v[7]);
        }
}

// ---------------- heads: combine partials + bias + relu, 1x1 heads, decode ----------------
__device__ __forceinline__ float clamp256(float v)
{
    return fminf(fmaxf(v, 0.f), 256.f);
}

template <int H, int W, int LEVEL>
__global__ void __launch_bounds__(256) heads_kernel(const float* __restrict__ conv_b,
                                                    const float* __restrict__ cls_w,
                                                    const float* __restrict__ cls_b,
                                                    const float* __restrict__ reg_w,
                                                    const float* __restrict__ reg_b)
{
    constexpr int HW = H * W;
    constexpr int NPOS = 4 * HW;
    const float* __restrict__ part = (LEVEL == 0) ? g_part0 : g_part1;

    int wid  = (blockIdx.x * blockDim.x + threadIdx.x) >> 5;
    int lane = threadIdx.x & 31;
    if (wid >= NPOS) return;

    const float* __restrict__ p0r = part + (size_t)wid * C_CH;
    const float* __restrict__ p1r = p0r + (size_t)NPOS * C_CH;
    const float* __restrict__ p2r = p1r + (size_t)NPOS * C_CH;
    float h[8];
#pragma unroll
    for (int k = 0; k < 8; ++k) {
        int c = lane + 32 * k;
        float v = p0r[c] + p1r[c] + p2r[c] + conv_b[c];
        h[k] = v > 0.f ? v : 0.f;
    }

    float red[15];
#pragma unroll
    for (int o = 0; o < 15; ++o) {
        const float* __restrict__ wv = (o < 3) ? (cls_w + o * C_CH) : (reg_w + (o - 3) * C_CH);
        float s = 0.f;
#pragma unroll
        for (int k = 0; k < 8; ++k) s = fmaf(h[k], wv[lane + 32 * k], s);
#pragma unroll
        for (int off = 16; off; off >>= 1) s += __shfl_xor_sync(0xFFFFFFFFu, s, off);
        red[o] = s;
    }

    if (lane < 3) {
        int a = lane;
        int b = wid / HW;
        int pp = wid % HW;
        int yy = pp / W, xx = pp % W;

        float logit = red[a] + cls_b[a];
        float score = 1.f / (1.f + expf(-logit));

        float ddx = red[3 + 4 * a + 0] + reg_b[4 * a + 0];
        float ddy = red[3 + 4 * a + 1] + reg_b[4 * a + 1];
        float ddw = red[3 + 4 * a + 2] + reg_b[4 * a + 2];
        float ddh = red[3 + 4 * a + 3] + reg_b[4 * a + 3];

        float stride = (LEVEL == 0) ? 8.f : 16.f;
        float cx0 = (xx + 0.5f) * stride;
        float cy0 = (yy + 0.5f) * stride;
        float wsv = c_ws[LEVEL][a], hsv = c_hs[LEVEL][a];
        float ax1 = clamp256(cx0 - 0.5f * wsv);
        float ay1 = clamp256(cy0 - 0.5f * hsv);
        float ax2 = clamp256(cx0 + 0.5f * wsv);
        float ay2 = clamp256(cy0 + 0.5f * hsv);
        float wa = ax2 - ax1, ha = ay2 - ay1;
        float cxa = ax1 + 0.5f * wa, cya = ay1 + 0.5f * ha;

        float cx = ddx * wa + cxa;
        float cy = ddy * ha + cya;
        float ww = expf(ddw) * wa;
        float hh = expf(ddh) * ha;
        float bx1 = clamp256(cx - 0.5f * ww);
        float by1 = clamp256(cy - 0.5f * hh);
        float bx2 = clamp256(cx + 0.5f * ww);
        float by2 = clamp256(cy + 0.5f * hh);

        int ai = pp * 3 + a;
        if (LEVEL == 0) {
            g_boxes0[b * (HW * 3) + ai] = make_float4(bx1, by1, bx2, by2);
            g_scores0[b * (HW * 3) + ai] = score;
        } else {
            g_boxes1[b * (HW * 3) + ai] = make_float4(bx1, by1, bx2, by2);
            g_scores1[b * (HW * 3) + ai] = score;
        }
    }
}

// ---------------- per-task stable sort: register-resident bitonic ----------------
// Also emits per-box areas for the mask kernel.
__global__ void __launch_bounds__(1024) sort_kernel()
{
    int task = blockIdx.x;
    int tid = threadIdx.x;
    int level = task >> 2, b = task & 3;
    int N = level ? 768 : 3072;
    const float* sc = level ? (g_scores1 + b * 768) : (g_scores0 + b * 3072);
    const float4* bx = level ? (g_boxes1 + b * 768) : (g_boxes0 + b * 3072);

    __shared__ unsigned long long sk[4096];

    unsigned long long v[4];
#pragma unroll
    for (int r = 0; r < 4; ++r) {
        int e = tid + (r << 10);
        v[r] = (e < N)
            ? ((((unsigned long long)__float_as_uint(sc[e])) << 32) |
               (unsigned long long)(0xFFFFFFFFu - (unsigned)e))
            : 0ull;
    }

    for (int k = 2; k <= 4096; k <<= 1) {
        for (int j = k >> 1; j > 0; j >>= 1) {
            if (j >= 1024) {
                int s = j >> 10;
#pragma unroll
                for (int r = 0; r < 4; ++r) {
                    int pr = r ^ s;
                    if (pr > r) {
                        int e = tid + (r << 10);
                        bool desc = ((e & k) == 0);
                        unsigned long long a = v[r], c = v[pr];
                        if (desc ? (a < c) : (a > c)) { v[r] = c; v[pr] = a; }
                    }
                }
            } else if (j >= 32) {
                __syncthreads();
#pragma unroll
                for (int r = 0; r < 4; ++r) sk[tid + (r << 10)] = v[r];
                __syncthreads();
#pragma unroll
                for (int r = 0; r < 4; ++r) {
                    int e = tid + (r << 10);
                    unsigned long long a = v[r];
                    unsigned long long c = sk[(tid ^ j) + (r << 10)];
                    bool desc = ((e & k) == 0);
                    bool left = ((tid & j) == 0);
                    bool take = left ? (desc ? (c > a) : (c < a))
                                     : (desc ? (c < a) : (c > a));
                    if (take) v[r] = c;
                }
            } else {
#pragma unroll
                for (int r = 0; r < 4; ++r) {
                    int e = tid + (r << 10);
                    unsigned long long a = v[r];
                    unsigned long long c = __shfl_xor_sync(0xFFFFFFFFu, a, j);
                    bool desc = ((e & k) == 0);
                    bool left = ((tid & j) == 0);
                    bool take = left ? (desc ? (c > a) : (c < a))
                                     : (desc ? (c < a) : (c > a));
                    if (take) v[r] = c;
                }
            }
        }
    }

#pragma unroll
    for (int r = 0; r < 4; ++r) {
        int e = tid + (r << 10);
        if (e < N) {
            unsigned long long kk = v[r];
            unsigned idx = 0xFFFFFFFFu - (unsigned)(kk & 0xFFFFFFFFu);
            float4 bb = bx[idx];
            g_sscores[task * 3072 + e] = __uint_as_float((unsigned)(kk >> 32));
            g_sboxes[task * 3072 + e] = bb;
            g_sarea[task * 3072 + e] = (bb.z - bb.x) * (bb.w - bb.y);
        }
    }
}

// ---------------- IoU suppression bitmask v3: warp-per-(i-chunk, j-word) ----------------
// Lane owns j = w*32+lane (bj, areaj in registers across 32 i's); bi/areai via
// LDG broadcast; suppress word assembled by ballot. Fast path uses
// d = fma(0.7,u,-inter) vs margin; exact-division fallback when any lane is
// ambiguous. Decision-for-decision identical to the reference.
// Lower-triangle (i,w) words are never written and stay zero (harmless: those
// bits cover only already-processed candidates).
__global__ void __launch_bounds__(256) mask_kernel()
{
    int task = blockIdx.y;
    int level = task >> 2;
    int chunks = level ? 24 : 96;       // both j-words and i-chunks of 32
    int warp = (blockIdx.x << 3) + (threadIdx.x >> 5);
    int lane = threadIdx.x & 31;
    int w  = warp / chunks;
    int ic = warp - w * chunks;
    if (w >= chunks || w < ic) return;  // L1 overhang + strict lower triangle

    const float4* __restrict__ sb = g_sboxes + task * 3072;
    const float*  __restrict__ sa = g_sarea + task * 3072;
    unsigned* __restrict__ mrow = g_mask + (size_t)task * 3072u * 96u;
    int words = chunks;

    int j = (w << 5) + lane;
    float4 bj = sb[j];
    float aj = sa[j];
    int i0 = ic << 5;

#pragma unroll 4
    for (int ii = 0; ii < 32; ++ii) {
        int i = i0 + ii;
        float4 bi = __ldg(&sb[i]);      // broadcast
        float ai = __ldg(&sa[i]);
        float xx1 = fmaxf(bi.x, bj.x), yy1 = fmaxf(bi.y, bj.y);
        float xx2 = fminf(bi.z, bj.z), yy2 = fminf(bi.w, bj.w);
        float iw = fmaxf(xx2 - xx1, 0.f), ih = fmaxf(yy2 - yy1, 0.f);
        float inter = iw * ih;
        float s = ai + aj;
        float u = s - inter;
        float d = fmaf(0.7f, u, -inter);   // d < 0  <=>  iou > 0.7 (up to rounding)
        float m = 1e-4f * s;               // margin >> rounding error
        bool amb = fabsf(d) <= m;
        bool sup;
        if (__any_sync(0xFFFFFFFFu, amb)) sup = (inter / u > 0.7f);  // exact reference path
        else                              sup = d < -m;
        unsigned bits = __ballot_sync(0xFFFFFFFFu, sup);
        if (lane == 0) mrow[(size_t)i * words + w] = bits;
    }
}

// ---------------- greedy NMS scan: smem-staged, replicated current word ----------------
__global__ void __launch_bounds__(128) nms_scan_kernel()
{
    int task = blockIdx.x;
    int level = task >> 2;
    const int words = level ? 24 : 96;
    const int wpg = 32 * words;
    const int u4pg = wpg / 4;

    float4* kb = g_kb + task * TOPK;
    float* ksc = g_ks + task * TOPK;
    int tid = threadIdx.x;
    int lane = tid & 31, wrp = tid >> 5;

    for (int s = tid; s < TOPK; s += 128) {
        kb[s] = make_float4(-1.f, -1.f, -1.f, -1.f);
        ksc[s] = -1.f;
    }

    __shared__ unsigned buf[2][32 * 96];
    __shared__ int s_stop;
    if (tid == 0) s_stop = 0;

    const unsigned* __restrict__ mask = g_mask + (size_t)task * 3072u * 96u;
    const float4* __restrict__ sb = g_sboxes + task * 3072;
    const float* __restrict__ ss = g_sscores + task * 3072;

    {
        const uint4* src = (const uint4*)mask;
        uint4* dst = (uint4*)buf[0];
        for (int t = tid; t < u4pg; t += 128) dst[t] = src[t];
    }
    __syncthreads();

    int kept = 0;
    unsigned rem0 = 0, rem1 = 0, rem2 = 0;   // distributed removed mask (word s*32+lane)

    for (int g = 0; g < words; ++g) {
        if (wrp > 0 && g + 1 < words) {
            const uint4* src = (const uint4*)(mask + (size_t)(g + 1) * wpg);
            uint4* dst = (uint4*)buf[(g + 1) & 1];
            for (int t = tid - 32; t < u4pg; t += 96) dst[t] = src[t];
        }
        if (wrp == 0) {
            const unsigned* __restrict__ cb = buf[g & 1];
            int sel = g >> 5;
            unsigned start = (sel == 0) ? rem0 : ((sel == 1) ? rem1 : rem2);
            unsigned cur = __shfl_sync(0xFFFFFFFFu, start, g & 31);
            unsigned avail = ~cur;
            while (avail) {
                int bit = __ffs(avail) - 1;
                int i = g * 32 + bit;
                if (lane == 0) { kb[kept] = sb[i]; ksc[kept] = ss[i]; }
                kept++;
                if (kept >= TOPK) { if (lane == 0) s_stop = 1; break; }
                const unsigned* __restrict__ row = cb + bit * words;
                cur |= row[g];                          // broadcast LDS: critical path
                if (lane < words)      rem0 |= row[lane];
                if (32 + lane < words) rem1 |= row[32 + lane];
                if (64 + lane < words) rem2 |= row[64 + lane];
                avail = ~cur & ((bit == 31) ? 0u : (0xFFFFFFFFu << (bit + 1)));
            }
        }
        __syncthreads();
        if (s_stop) break;
    }
}

// ---------------- per-image stable merge of the two levels ----------------
__global__ void __launch_bounds__(512) merge_kernel(float4* __restrict__ out)
{
    int b = blockIdx.x;
    int p = blockIdx.y * blockDim.x + threadIdx.x;
    if (p >= 2 * TOPK) return;
    const float* __restrict__ A = g_ks + b * TOPK;
    const float* __restrict__ B = g_ks + (4 + b) * TOPK;

    int lo = p > TOPK ? p - TOPK : 0;
    int hi = p < TOPK ? p : TOPK;
    while (lo < hi) {
        int i = (lo + hi) >> 1;
        int j = p - i;
        if (A[i] >= B[j - 1]) lo = i + 1;  // tie -> A first (stable)
        else hi = i;
    }
    int i = lo, j = p - i;
    bool takeA = (i < TOPK) && (j >= TOPK || A[i] >= B[j]);
    float4 v = takeA ? g_kb[b * TOPK + i] : g_kb[(4 + b) * TOPK + j];
    out[b * 2 * TOPK + p] = v;
}

// ---------------- launch ----------------
// conv0 stays in the profiled 4th slot to verify the dup-weight change.
extern "C" void kernel_launch(void* const* d_in, const int* in_sizes, int n_in,
                              void* d_out, int out_size)
{
    const float* feat0  = (const float*)d_in[0];
    const float* feat1  = (const float*)d_in[1];
    const float* conv_w = (const float*)d_in[2];
    const float* conv_b = (const float*)d_in[3];
    const float* cls_w  = (const float*)d_in[4];
    const float* cls_b  = (const float*)d_in[5];
    const float* reg_w  = (const float*)d_in[6];
    const float* reg_b  = (const float*)d_in[7];
    (void)in_sizes; (void)n_in; (void)out_size;

    wtrans_kernel<<<(C_CH * C_CH * 9 + 255) / 256, 256>>>(conv_w);            // 1

    conv3x3_kernel<16, 16, 1><<<dim3(8, 4, 3), 128>>>(feat1);                 // 2
    heads_kernel<16, 16, 1><<<128, 256>>>(conv_b, cls_w, cls_b, reg_w, reg_b);// 3

    conv3x3_kernel<32, 32, 0><<<dim3(32, 4, 3), 128>>>(feat0);                // 4 (profiled)
    heads_kernel<32, 32, 0><<<512, 256>>>(conv_b, cls_w, cls_b, reg_w, reg_b);// 5

    sort_kernel<<<8, 1024>>>();                                               // 6

    mask_kernel<<<dim3(1152, 8), 256>>>();                                    // 7

    nms_scan_kernel<<<8, 128>>>();                                            // 8

    merge_kernel<<<dim3(4, 4), 512>>>((float4*)d_out);                        // 9
}

// round 12
// speedup vs baseline: 1.0492x; 1.0492x over previous
#include <cuda_runtime.h>
#include <cuda_bf16.h>
#include <math.h>
#include <stdint.h>

// ---------------- problem constants ----------------
#define C_CH   256
#define TOPK   1000

__device__ __constant__ float c_ws[2][3] = {
    {90.50966799187809f, 64.0f, 45.254833995939045f},
    {181.01933598375618f, 128.0f, 90.50966799187809f}};
__device__ __constant__ float c_hs[2][3] = {
    {45.254833995939045f, 64.0f, 90.50966799187809f},
    {90.50966799187809f, 128.0f, 181.01933598375618f}};

// ---------------- device scratch (static, no allocs) ----------------
__device__ float  g_part0[3 * 4096 * C_CH];      // level0 conv partials (per tap-row group)
__device__ float  g_part1[3 * 1024 * C_CH];      // level1 conv partials
__device__ float  g_wt[9 * C_CH * C_CH];         // transposed conv weights [tap][ci][co]
__device__ float4 g_boxes0[4 * 3072];
__device__ float4 g_boxes1[4 * 768];
__device__ float  g_scores0[4 * 3072];
__device__ float  g_scores1[4 * 768];
__device__ float4 g_sboxes[8 * 3072];            // per-task sorted boxes
__device__ float  g_sscores[8 * 3072];           // per-task sorted scores
__device__ unsigned g_mask[8u * 3072u * 96u];    // IoU>thresh bitmask, row-major per task
__device__ float4 g_kb[8 * TOPK];                // kept boxes per task
__device__ float  g_ks[8 * TOPK];                // kept scores per task

// ---------------- small PTX helpers ----------------
__device__ __forceinline__ void fma2(unsigned long long& d, unsigned long long a,
                                     unsigned long long b)
{
    asm("fma.rn.f32x2 %0, %1, %2, %0;" : "+l"(d) : "l"(a), "l"(b));
}
__device__ __forceinline__ unsigned long long pack_dup(float v)
{
    unsigned long long r;
    unsigned u = __float_as_uint(v);
    asm("mov.b64 %0, {%1, %1};" : "=l"(r) : "r"(u));
    return r;
}
__device__ __forceinline__ void cp_async16(uint32_t dst, const void* src)
{
    asm volatile("cp.async.cg.shared.global [%0], [%1], 16;" :: "r"(dst), "l"(src));
}
__device__ __forceinline__ void cp_async4(uint32_t dst, const void* src, bool ok)
{
    int sz = ok ? 4 : 0;
    asm volatile("cp.async.ca.shared.global [%0], [%1], 4, %2;" :: "r"(dst), "l"(src), "r"(sz));
}

// ---------------- weight transpose ----------------
__global__ void wtrans_kernel(const float* __restrict__ w)
{
    int idx = blockIdx.x * blockDim.x + threadIdx.x;
    if (idx >= C_CH * C_CH * 9) return;
    int co  = idx / (C_CH * 9);
    int r   = idx % (C_CH * 9);
    int ci  = r / 9;
    int tap = r % 9;
    g_wt[(tap * C_CH + ci) * C_CH + co] = w[idx];
}

// ---------------- 3x3 conv, split-K over tap rows, f32x2 packed FMA ----------------
// EXACT round-8/10 kernel (128 regs, zero headroom — do not widen operands).
template <int H, int W, int LEVEL>
__global__ void __launch_bounds__(128, 4) conv3x3_kernel(const float* __restrict__ xin)
{
    constexpr int HW = H * W;
    constexpr int NSLICE = 48;   // 3 taps x 16-deep ci slices
    float* __restrict__ outp = ((LEVEL == 0) ? g_part0 : g_part1)
                               + (size_t)blockIdx.z * (4 * HW * C_CH);

    const int tid  = threadIdx.x;
    const int n0   = blockIdx.x * 128;  // 128 | HW, never crosses image
    const int co0  = blockIdx.y * 64;
    const int b    = n0 / HW;
    const int p0   = n0 % HW;
    const int cth  = tid & 7;           // 8 co-groups of 8
    const int pth  = tid >> 3;          // 16 pos-groups of 8
    const int tap0 = blockIdx.z * 3;
    const float* __restrict__ xb = xin + (size_t)b * C_CH * HW;

    __shared__ float As[3][16][64];
    __shared__ float Bs[3][16][128];
    uint32_t sA = (uint32_t)__cvta_generic_to_shared(&As[0][0][0]);
    uint32_t sB = (uint32_t)__cvta_generic_to_shared(&Bs[0][0][0]);

    const int p  = p0 + tid;
    const int py = p / W, px = p % W;

    unsigned long long acc[8][4];
#pragma unroll
    for (int i = 0; i < 8; ++i)
#pragma unroll
        for (int j = 0; j < 4; ++j) acc[i][j] = 0ull;

#define ISSUE_SLICE(s)                                                           \
    {                                                                            \
        int buf = (s) % 3;                                                       \
        int tap = tap0 + ((s) >> 4);                                             \
        int ci0 = ((s) & 15) << 4;                                               \
        int dy = tap / 3 - 1, dx = tap % 3 - 1;                                  \
        const float* wbase = g_wt + ((size_t)tap * C_CH + ci0) * C_CH + co0;     \
        _Pragma("unroll")                                                        \
        for (int r = 0; r < 2; ++r) {                                            \
            int f4 = tid + 128 * r;                                              \
            int kk = f4 >> 4, c4 = f4 & 15;                                      \
            cp_async16(sA + buf * (16*64*4) + (kk * 64 + c4 * 4) * 4,            \
                       wbase + (size_t)kk * C_CH + c4 * 4);                      \
        }                                                                        \
        int ys = py + dy, xs = px + dx;                                          \
        bool ok = ((unsigned)ys < (unsigned)H) && ((unsigned)xs < (unsigned)W);  \
        const float* bsrc = xb + (size_t)ci0 * HW + (ys * W + xs);               \
        _Pragma("unroll")                                                        \
        for (int r = 0; r < 16; ++r)                                             \
            cp_async4(sB + buf * (16*128*4) + (r * 128 + tid) * 4,               \
                      bsrc + (size_t)r * HW, ok);                                \
        asm volatile("cp.async.commit_group;");                                  \
    }

    ISSUE_SLICE(0);
    ISSUE_SLICE(1);

    for (int s = 0; s < NSLICE; ++s) {
        if (s + 2 < NSLICE) {
            asm volatile("cp.async.wait_group 1;");   // slice s arrived
            __syncthreads();                          // publish s; frees buf (s-1)%3
            ISSUE_SLICE(s + 2);                       // writes buf (s+2)%3 == (s-1)%3
        } else {
            asm volatile("cp.async.wait_group %0;" :: "n"(0) : "memory");
            __syncthreads();
        }
        const float (*Ab)[64]  = As[s % 3];
        const float (*Bb)[128] = Bs[s % 3];
#pragma unroll
        for (int kk = 0; kk < 16; ++kk) {
            float4 a0 = *(const float4*)&Ab[kk][cth * 8];
            float4 a1 = *(const float4*)&Ab[kk][cth * 8 + 4];
            ulonglong2 bl0 = *(const ulonglong2*)&Bb[kk][pth * 8];
            ulonglong2 bl1 = *(const ulonglong2*)&Bb[kk][pth * 8 + 4];
            unsigned long long bb[4] = {bl0.x, bl0.y, bl1.x, bl1.y};
            float av[8] = {a0.x, a0.y, a0.z, a0.w, a1.x, a1.y, a1.z, a1.w};
#pragma unroll
            for (int i = 0; i < 8; ++i) {
                unsigned long long ad = pack_dup(av[i]);
#pragma unroll
                for (int j = 0; j < 4; ++j) fma2(acc[i][j], ad, bb[j]);
            }
        }
    }
#undef ISSUE_SLICE

#pragma unroll
    for (int j = 0; j < 4; ++j)
#pragma unroll
        for (int h = 0; h < 2; ++h) {
            int n = n0 + pth * 8 + j * 2 + h;
            float v[8];
#pragma unroll
            for (int i = 0; i < 8; ++i) {
                float2 f = *reinterpret_cast<float2*>(&acc[i][j]);
                v[i] = h ? f.y : f.x;
            }
            *(float4*)&outp[(size_t)n * C_CH + co0 + cth * 8] =
                make_float4(v[0], v[1], v[2], v[3]);
            *(float4*)&outp[(size_t)n * C_CH + co0 + cth * 8 + 4] =
                make_float4(v[4], v[5], v[6], v[7]);
        }
}

// ---------------- heads: combine partials + bias + relu, 1x1 heads, decode ----------------
__device__ __forceinline__ float clamp256(float v)
{
    return fminf(fmaxf(v, 0.f), 256.f);
}

template <int H, int W, int LEVEL>
__global__ void __launch_bounds__(256) heads_kernel(const float* __restrict__ conv_b,
                                                    const float* __restrict__ cls_w,
                                                    const float* __restrict__ cls_b,
                                                    const float* __restrict__ reg_w,
                                                    const float* __restrict__ reg_b)
{
    constexpr int HW = H * W;
    constexpr int NPOS = 4 * HW;
    const float* __restrict__ part = (LEVEL == 0) ? g_part0 : g_part1;

    int wid  = (blockIdx.x * blockDim.x + threadIdx.x) >> 5;
    int lane = threadIdx.x & 31;
    if (wid >= NPOS) return;

    const float* __restrict__ p0r = part + (size_t)wid * C_CH;
    const float* __restrict__ p1r = p0r + (size_t)NPOS * C_CH;
    const float* __restrict__ p2r = p1r + (size_t)NPOS * C_CH;
    float h[8];
#pragma unroll
    for (int k = 0; k < 8; ++k) {
        int c = lane + 32 * k;
        float v = p0r[c] + p1r[c] + p2r[c] + conv_b[c];
        h[k] = v > 0.f ? v : 0.f;
    }

    float red[15];
#pragma unroll
    for (int o = 0; o < 15; ++o) {
        const float* __restrict__ wv = (o < 3) ? (cls_w + o * C_CH) : (reg_w + (o - 3) * C_CH);
        float s = 0.f;
#pragma unroll
        for (int k = 0; k < 8; ++k) s = fmaf(h[k], wv[lane + 32 * k], s);
#pragma unroll
        for (int off = 16; off; off >>= 1) s += __shfl_xor_sync(0xFFFFFFFFu, s, off);
        red[o] = s;
    }

    if (lane < 3) {
        int a = lane;
        int b = wid / HW;
        int pp = wid % HW;
        int yy = pp / W, xx = pp % W;

        float logit = red[a] + cls_b[a];
        float score = 1.f / (1.f + expf(-logit));

        float ddx = red[3 + 4 * a + 0] + reg_b[4 * a + 0];
        float ddy = red[3 + 4 * a + 1] + reg_b[4 * a + 1];
        float ddw = red[3 + 4 * a + 2] + reg_b[4 * a + 2];
        float ddh = red[3 + 4 * a + 3] + reg_b[4 * a + 3];

        float stride = (LEVEL == 0) ? 8.f : 16.f;
        float cx0 = (xx + 0.5f) * stride;
        float cy0 = (yy + 0.5f) * stride;
        float wsv = c_ws[LEVEL][a], hsv = c_hs[LEVEL][a];
        float ax1 = clamp256(cx0 - 0.5f * wsv);
        float ay1 = clamp256(cy0 - 0.5f * hsv);
        float ax2 = clamp256(cx0 + 0.5f * wsv);
        float ay2 = clamp256(cy0 + 0.5f * hsv);
        float wa = ax2 - ax1, ha = ay2 - ay1;
        float cxa = ax1 + 0.5f * wa, cya = ay1 + 0.5f * ha;

        float cx = ddx * wa + cxa;
        float cy = ddy * ha + cya;
        float ww = expf(ddw) * wa;
        float hh = expf(ddh) * ha;
        float bx1 = clamp256(cx - 0.5f * ww);
        float by1 = clamp256(cy - 0.5f * hh);
        float bx2 = clamp256(cx + 0.5f * ww);
        float by2 = clamp256(cy + 0.5f * hh);

        int ai = pp * 3 + a;
        if (LEVEL == 0) {
            g_boxes0[b * (HW * 3) + ai] = make_float4(bx1, by1, bx2, by2);
            g_scores0[b * (HW * 3) + ai] = score;
        } else {
            g_boxes1[b * (HW * 3) + ai] = make_float4(bx1, by1, bx2, by2);
            g_scores1[b * (HW * 3) + ai] = score;
        }
    }
}

// ---------------- per-task stable sort: register-resident bitonic ----------------
__global__ void __launch_bounds__(1024) sort_kernel()
{
    int task = blockIdx.x;
    int tid = threadIdx.x;
    int level = task >> 2, b = task & 3;
    int N = level ? 768 : 3072;
    const float* sc = level ? (g_scores1 + b * 768) : (g_scores0 + b * 3072);
    const float4* bx = level ? (g_boxes1 + b * 768) : (g_boxes0 + b * 3072);

    __shared__ unsigned long long sk[4096];

    unsigned long long v[4];
#pragma unroll
    for (int r = 0; r < 4; ++r) {
        int e = tid + (r << 10);
        v[r] = (e < N)
            ? ((((unsigned long long)__float_as_uint(sc[e])) << 32) |
               (unsigned long long)(0xFFFFFFFFu - (unsigned)e))
            : 0ull;
    }

    for (int k = 2; k <= 4096; k <<= 1) {
        for (int j = k >> 1; j > 0; j >>= 1) {
            if (j >= 1024) {
                int s = j >> 10;
#pragma unroll
                for (int r = 0; r < 4; ++r) {
                    int pr = r ^ s;
                    if (pr > r) {
                        int e = tid + (r << 10);
                        bool desc = ((e & k) == 0);
                        unsigned long long a = v[r], c = v[pr];
                        if (desc ? (a < c) : (a > c)) { v[r] = c; v[pr] = a; }
                    }
                }
            } else if (j >= 32) {
                __syncthreads();
#pragma unroll
                for (int r = 0; r < 4; ++r) sk[tid + (r << 10)] = v[r];
                __syncthreads();
#pragma unroll
                for (int r = 0; r < 4; ++r) {
                    int e = tid + (r << 10);
                    unsigned long long a = v[r];
                    unsigned long long c = sk[(tid ^ j) + (r << 10)];
                    bool desc = ((e & k) == 0);
                    bool left = ((tid & j) == 0);
                    bool take = left ? (desc ? (c > a) : (c < a))
                                     : (desc ? (c < a) : (c > a));
                    if (take) v[r] = c;
                }
            } else {
#pragma unroll
                for (int r = 0; r < 4; ++r) {
                    int e = tid + (r << 10);
                    unsigned long long a = v[r];
                    unsigned long long c = __shfl_xor_sync(0xFFFFFFFFu, a, j);
                    bool desc = ((e & k) == 0);
                    bool left = ((tid & j) == 0);
                    bool take = left ? (desc ? (c > a) : (c < a))
                                     : (desc ? (c < a) : (c > a));
                    if (take) v[r] = c;
                }
            }
        }
    }

#pragma unroll
    for (int r = 0; r < 4; ++r) {
        int e = tid + (r << 10);
        if (e < N) {
            unsigned long long kk = v[r];
            unsigned idx = 0xFFFFFFFFu - (unsigned)(kk & 0xFFFFFFFFu);
            g_sscores[task * 3072 + e] = __uint_as_float((unsigned)(kk >> 32));
            g_sboxes[task * 3072 + e] = bx[idx];
        }
    }
}

// ---------------- IoU suppression bitmask (division-free fast path) ----------------
__global__ void __launch_bounds__(256) mask_kernel()
{
    int task = blockIdx.y;
    int level = task >> 2;
    int N = level ? 768 : 3072;
    int words = level ? 24 : 96;
    int idx = blockIdx.x * blockDim.x + threadIdx.x;
    if (idx >= N * words) return;
    int w = idx / N;
    int i = idx % N;
    int j0 = w * 32;

    unsigned* dst = g_mask + (size_t)task * 3072u * 96u + (size_t)i * words + w;
    if (j0 + 31 <= i) { *dst = 0u; return; }   // scan only consumes j > i bits

    const float4* __restrict__ sb = g_sboxes + task * 3072;
    float4 bi = sb[i];
    float areai = (bi.z - bi.x) * (bi.w - bi.y);

    unsigned bits = 0, amb = 0;
#pragma unroll 4
    for (int jj = 0; jj < 32; ++jj) {
        float4 bj = __ldg(&sb[j0 + jj]);
        float xx1 = fmaxf(bi.x, bj.x), yy1 = fmaxf(bi.y, bj.y);
        float xx2 = fminf(bi.z, bj.z), yy2 = fminf(bi.w, bj.w);
        float iw = xx2 - xx1, ih = yy2 - yy1;
        float areaj = (bj.z - bj.x) * (bj.w - bj.y);
        float inter = iw * ih;
        float s = areai + areaj;
        float u = s - inter;
        float d = fmaf(0.7f, u, -inter);   // d < 0  <=>  iou > 0.7 (up to rounding)
        float m = 1e-4f * s;               // safety band >> all rounding error
        bool pos = (iw > 0.f) && (ih > 0.f);
        if (pos && (d < -m)) bits |= (1u << jj);
        if (pos && (fabsf(d) <= m)) amb |= (1u << jj);
    }
    while (amb) {
        int jj = __ffs(amb) - 1;
        amb &= amb - 1;
        float4 bj = __ldg(&sb[j0 + jj]);
        float xx1 = fmaxf(bi.x, bj.x), yy1 = fmaxf(bi.y, bj.y);
        float xx2 = fminf(bi.z, bj.z), yy2 = fminf(bi.w, bj.w);
        float iw = fmaxf(xx2 - xx1, 0.f), ih = fmaxf(yy2 - yy1, 0.f);
        float inter = iw * ih;
        float areaj = (bj.z - bj.x) * (bj.w - bj.y);
        float u = (areai + areaj) - inter;
        if (inter / u > 0.7f) bits |= (1u << jj);
        else                  bits &= ~(1u << jj);
    }
    *dst = bits;
}

// ---------------- greedy NMS scan: smem-staged, replicated current word ----------------
// IDEMPOTENT: reads g_mask/g_sboxes/g_sscores, writes g_kb/g_ks. A duplicate
// launch early in the graph reads last-replay data (identical values) and is
// overwritten by the real post-mask launch — final state always correct.
__global__ void __launch_bounds__(128) nms_scan_kernel()
{
    int task = blockIdx.x;
    int level = task >> 2;
    const int words = level ? 24 : 96;
    const int wpg = 32 * words;
    const int u4pg = wpg / 4;

    float4* kb = g_kb + task * TOPK;
    float* ksc = g_ks + task * TOPK;
    int tid = threadIdx.x;
    int lane = tid & 31, wrp = tid >> 5;

    for (int s = tid; s < TOPK; s += 128) {
        kb[s] = make_float4(-1.f, -1.f, -1.f, -1.f);
        ksc[s] = -1.f;
    }

    __shared__ unsigned buf[2][32 * 96];
    __shared__ int s_stop;
    if (tid == 0) s_stop = 0;

    const unsigned* __restrict__ mask = g_mask + (size_t)task * 3072u * 96u;
    const float4* __restrict__ sb = g_sboxes + task * 3072;
    const float* __restrict__ ss = g_sscores + task * 3072;

    {
        const uint4* src = (const uint4*)mask;
        uint4* dst = (uint4*)buf[0];
        for (int t = tid; t < u4pg; t += 128) dst[t] = src[t];
    }
    __syncthreads();

    int kept = 0;
    unsigned rem0 = 0, rem1 = 0, rem2 = 0;   // distributed removed mask (word s*32+lane)

    for (int g = 0; g < words; ++g) {
        if (wrp > 0 && g + 1 < words) {
            const uint4* src = (const uint4*)(mask + (size_t)(g + 1) * wpg);
            uint4* dst = (uint4*)buf[(g + 1) & 1];
            for (int t = tid - 32; t < u4pg; t += 96) dst[t] = src[t];
        }
        if (wrp == 0) {
            const unsigned* __restrict__ cb = buf[g & 1];
            int sel = g >> 5;
            unsigned start = (sel == 0) ? rem0 : ((sel == 1) ? rem1 : rem2);
            unsigned cur = __shfl_sync(0xFFFFFFFFu, start, g & 31);
            unsigned avail = ~cur;
            while (avail) {
                int bit = __ffs(avail) - 1;
                int i = g * 32 + bit;
                if (lane == 0) { kb[kept] = sb[i]; ksc[kept] = ss[i]; }
                kept++;
                if (kept >= TOPK) { if (lane == 0) s_stop = 1; break; }
                const unsigned* __restrict__ row = cb + bit * words;
                cur |= row[g];                          // broadcast LDS: critical path
                if (lane < words)      rem0 |= row[lane];
                if (32 + lane < words) rem1 |= row[32 + lane];
                if (64 + lane < words) rem2 |= row[64 + lane];
                avail = ~cur & ((bit == 31) ? 0u : (0xFFFFFFFFu << (bit + 1)));
            }
        }
        __syncthreads();
        if (s_stop) break;
    }
}

// ---------------- per-image stable merge of the two levels ----------------
__global__ void __launch_bounds__(512) merge_kernel(float4* __restrict__ out)
{
    int b = blockIdx.x;
    int p = blockIdx.y * blockDim.x + threadIdx.x;
    if (p >= 2 * TOPK) return;
    const float* __restrict__ A = g_ks + b * TOPK;
    const float* __restrict__ B = g_ks + (4 + b) * TOPK;

    int lo = p > TOPK ? p - TOPK : 0;
    int hi = p < TOPK ? p : TOPK;
    while (lo < hi) {
        int i = (lo + hi) >> 1;
        int j = p - i;
        if (A[i] >= B[j - 1]) lo = i + 1;  // tie -> A first (stable)
        else hi = i;
    }
    int i = lo, j = p - i;
    bool takeA = (i < TOPK) && (j >= TOPK || A[i] >= B[j]);
    float4 v = takeA ? g_kb[b * TOPK + i] : g_kb[(4 + b) * TOPK + j];
    out[b * 2 * TOPK + p] = v;
}

// ---------------- launch ----------------
// Slot 4 = DUPLICATE nms_scan for profiling only (idempotent; real scan at
// slot 9 overwrites g_kb/g_ks with correct values on every execution).
extern "C" void kernel_launch(void* const* d_in, const int* in_sizes, int n_in,
                              void* d_out, int out_size)
{
    const float* feat0  = (const float*)d_in[0];
    const float* feat1  = (const float*)d_in[1];
    const float* conv_w = (const float*)d_in[2];
    const float* conv_b = (const float*)d_in[3];
    const float* cls_w  = (const float*)d_in[4];
    const float* cls_b  = (const float*)d_in[5];
    const float* reg_w  = (const float*)d_in[6];
    const float* reg_b  = (const float*)d_in[7];
    (void)in_sizes; (void)n_in; (void)out_size;

    wtrans_kernel<<<(C_CH * C_CH * 9 + 255) / 256, 256>>>(conv_w);            // 1

    conv3x3_kernel<16, 16, 1><<<dim3(8, 4, 3), 128>>>(feat1);                 // 2
    heads_kernel<16, 16, 1><<<128, 256>>>(conv_b, cls_w, cls_b, reg_w, reg_b);// 3

    nms_scan_kernel<<<8, 128>>>();                                            // 4 (profiled DUP)

    conv3x3_kernel<32, 32, 0><<<dim3(32, 4, 3), 128>>>(feat0);                // 5
    heads_kernel<32, 32, 0><<<512, 256>>>(conv_b, cls_w, cls_b, reg_w, reg_b);// 6

    sort_kernel<<<8, 1024>>>();                                               // 7

    mask_kernel<<<dim3((96 * 3072 + 255) / 256, 8), 256>>>();                 // 8

    nms_scan_kernel<<<8, 128>>>();                                            // 9 (real)

    merge_kernel<<<dim3(4, 4), 512>>>((float4*)d_out);                        // 10
}

// round 13
// speedup vs baseline: 2.2864x; 2.1791x over previous
#include <cuda_runtime.h>
#include <cuda_bf16.h>
#include <math.h>
#include <stdint.h>

// ---------------- problem constants ----------------
#define C_CH   256
#define TOPK   1000

__device__ __constant__ float c_ws[2][3] = {
    {90.50966799187809f, 64.0f, 45.254833995939045f},
    {181.01933598375618f, 128.0f, 90.50966799187809f}};
__device__ __constant__ float c_hs[2][3] = {
    {45.254833995939045f, 64.0f, 90.50966799187809f},
    {90.50966799187809f, 128.0f, 181.01933598375618f}};

// ---------------- device scratch (static, no allocs) ----------------
__device__ float  g_part0[3 * 4096 * C_CH];      // level0 conv partials (per tap-row group)
__device__ float  g_part1[3 * 1024 * C_CH];      // level1 conv partials
__device__ float  g_wt[9 * C_CH * C_CH];         // transposed conv weights [tap][ci][co]
__device__ float4 g_boxes0[4 * 3072];
__device__ float4 g_boxes1[4 * 768];
__device__ float  g_scores0[4 * 3072];
__device__ float  g_scores1[4 * 768];
__device__ float4 g_sboxes[8 * 3072];            // per-task sorted boxes
__device__ float  g_sscores[8 * 3072];           // per-task sorted scores
__device__ unsigned g_mask[8u * 3072u * 96u];    // IoU>thresh bitmask, row-major per task
__device__ float4 g_kb[8 * TOPK];                // kept boxes per task
__device__ float  g_ks[8 * TOPK];                // kept scores per task

// ---------------- small PTX helpers ----------------
__device__ __forceinline__ void fma2(unsigned long long& d, unsigned long long a,
                                     unsigned long long b)
{
    asm("fma.rn.f32x2 %0, %1, %2, %0;" : "+l"(d) : "l"(a), "l"(b));
}
__device__ __forceinline__ unsigned long long pack_dup(float v)
{
    unsigned long long r;
    unsigned u = __float_as_uint(v);
    asm("mov.b64 %0, {%1, %1};" : "=l"(r) : "r"(u));
    return r;
}
__device__ __forceinline__ void cp_async16(uint32_t dst, const void* src)
{
    asm volatile("cp.async.cg.shared.global [%0], [%1], 16;" :: "r"(dst), "l"(src));
}
__device__ __forceinline__ void cp_async4(uint32_t dst, const void* src, bool ok)
{
    int sz = ok ? 4 : 0;
    asm volatile("cp.async.ca.shared.global [%0], [%1], 4, %2;" :: "r"(dst), "l"(src), "r"(sz));
}

// ---------------- weight transpose ----------------
__global__ void wtrans_kernel(const float* __restrict__ w)
{
    int idx = blockIdx.x * blockDim.x + threadIdx.x;
    if (idx >= C_CH * C_CH * 9) return;
    int co  = idx / (C_CH * 9);
    int r   = idx % (C_CH * 9);
    int ci  = r / 9;
    int tap = r % 9;
    g_wt[(tap * C_CH + ci) * C_CH + co] = w[idx];
}

// ---------------- 3x3 conv, split-K over tap rows, f32x2 packed FMA ----------------
// EXACT round-8/10 kernel (128 regs, zero headroom — do not widen operands).
template <int H, int W, int LEVEL>
__global__ void __launch_bounds__(128, 4) conv3x3_kernel(const float* __restrict__ xin)
{
    constexpr int HW = H * W;
    constexpr int NSLICE = 48;   // 3 taps x 16-deep ci slices
    float* __restrict__ outp = ((LEVEL == 0) ? g_part0 : g_part1)
                               + (size_t)blockIdx.z * (4 * HW * C_CH);

    const int tid  = threadIdx.x;
    const int n0   = blockIdx.x * 128;  // 128 | HW, never crosses image
    const int co0  = blockIdx.y * 64;
    const int b    = n0 / HW;
    const int p0   = n0 % HW;
    const int cth  = tid & 7;           // 8 co-groups of 8
    const int pth  = tid >> 3;          // 16 pos-groups of 8
    const int tap0 = blockIdx.z * 3;
    const float* __restrict__ xb = xin + (size_t)b * C_CH * HW;

    __shared__ float As[3][16][64];
    __shared__ float Bs[3][16][128];
    uint32_t sA = (uint32_t)__cvta_generic_to_shared(&As[0][0][0]);
    uint32_t sB = (uint32_t)__cvta_generic_to_shared(&Bs[0][0][0]);

    const int p  = p0 + tid;
    const int py = p / W, px = p % W;

    unsigned long long acc[8][4];
#pragma unroll
    for (int i = 0; i < 8; ++i)
#pragma unroll
        for (int j = 0; j < 4; ++j) acc[i][j] = 0ull;

#define ISSUE_SLICE(s)                                                           \
    {                                                                            \
        int buf = (s) % 3;                                                       \
        int tap = tap0 + ((s) >> 4);                                             \
        int ci0 = ((s) & 15) << 4;                                               \
        int dy = tap / 3 - 1, dx = tap % 3 - 1;                                  \
        const float* wbase = g_wt + ((size_t)tap * C_CH + ci0) * C_CH + co0;     \
        _Pragma("unroll")                                                        \
        for (int r = 0; r < 2; ++r) {                                            \
            int f4 = tid + 128 * r;                                              \
            int kk = f4 >> 4, c4 = f4 & 15;                                      \
            cp_async16(sA + buf * (16*64*4) + (kk * 64 + c4 * 4) * 4,            \
                       wbase + (size_t)kk * C_CH + c4 * 4);                      \
        }                                                                        \
        int ys = py + dy, xs = px + dx;                                          \
        bool ok = ((unsigned)ys < (unsigned)H) && ((unsigned)xs < (unsigned)W);  \
        const float* bsrc = xb + (size_t)ci0 * HW + (ys * W + xs);               \
        _Pragma("unroll")                                                        \
        for (int r = 0; r < 16; ++r)                                             \
            cp_async4(sB + buf * (16*128*4) + (r * 128 + tid) * 4,               \
                      bsrc + (size_t)r * HW, ok);                                \
        asm volatile("cp.async.commit_group;");                                  \
    }

    ISSUE_SLICE(0);
    ISSUE_SLICE(1);

    for (int s = 0; s < NSLICE; ++s) {
        if (s + 2 < NSLICE) {
            asm volatile("cp.async.wait_group 1;");   // slice s arrived
            __syncthreads();                          // publish s; frees buf (s-1)%3
            ISSUE_SLICE(s + 2);                       // writes buf (s+2)%3 == (s-1)%3
        } else {
            asm volatile("cp.async.wait_group %0;" :: "n"(0) : "memory");
            __syncthreads();
        }
        const float (*Ab)[64]  = As[s % 3];
        const float (*Bb)[128] = Bs[s % 3];
#pragma unroll
        for (int kk = 0; kk < 16; ++kk) {
            float4 a0 = *(const float4*)&Ab[kk][cth * 8];
            float4 a1 = *(const float4*)&Ab[kk][cth * 8 + 4];
            ulonglong2 bl0 = *(const ulonglong2*)&Bb[kk][pth * 8];
            ulonglong2 bl1 = *(const ulonglong2*)&Bb[kk][pth * 8 + 4];
            unsigned long long bb[4] = {bl0.x, bl0.y, bl1.x, bl1.y};
            float av[8] = {a0.x, a0.y, a0.z, a0.w, a1.x, a1.y, a1.z, a1.w};
#pragma unroll
            for (int i = 0; i < 8; ++i) {
                unsigned long long ad = pack_dup(av[i]);
#pragma unroll
                for (int j = 0; j < 4; ++j) fma2(acc[i][j], ad, bb[j]);
            }
        }
    }
#undef ISSUE_SLICE

#pragma unroll
    for (int j = 0; j < 4; ++j)
#pragma unroll
        for (int h = 0; h < 2; ++h) {
            int n = n0 + pth * 8 + j * 2 + h;
            float v[8];
#pragma unroll
            for (int i = 0; i < 8; ++i) {
                float2 f = *reinterpret_cast<float2*>(&acc[i][j]);
                v[i] = h ? f.y : f.x;
            }
            *(float4*)&outp[(size_t)n * C_CH + co0 + cth * 8] =
                make_float4(v[0], v[1], v[2], v[3]);
            *(float4*)&outp[(size_t)n * C_CH + co0 + cth * 8 + 4] =
                make_float4(v[4], v[5], v[6], v[7]);
        }
}

// ---------------- heads: combine partials + bias + relu, 1x1 heads, decode ----------------
__device__ __forceinline__ float clamp256(float v)
{
    return fminf(fmaxf(v, 0.f), 256.f);
}

template <int H, int W, int LEVEL>
__global__ void __launch_bounds__(256) heads_kernel(const float* __restrict__ conv_b,
                                                    const float* __restrict__ cls_w,
                                                    const float* __restrict__ cls_b,
                                                    const float* __restrict__ reg_w,
                                                    const float* __restrict__ reg_b)
{
    constexpr int HW = H * W;
    constexpr int NPOS = 4 * HW;
    const float* __restrict__ part = (LEVEL == 0) ? g_part0 : g_part1;

    int wid  = (blockIdx.x * blockDim.x + threadIdx.x) >> 5;
    int lane = threadIdx.x & 31;
    if (wid >= NPOS) return;

    const float* __restrict__ p0r = part + (size_t)wid * C_CH;
    const float* __restrict__ p1r = p0r + (size_t)NPOS * C_CH;
    const float* __restrict__ p2r = p1r + (size_t)NPOS * C_CH;
    float h[8];
#pragma unroll
    for (int k = 0; k < 8; ++k) {
        int c = lane + 32 * k;
        float v = p0r[c] + p1r[c] + p2r[c] + conv_b[c];
        h[k] = v > 0.f ? v : 0.f;
    }

    float red[15];
#pragma unroll
    for (int o = 0; o < 15; ++o) {
        const float* __restrict__ wv = (o < 3) ? (cls_w + o * C_CH) : (reg_w + (o - 3) * C_CH);
        float s = 0.f;
#pragma unroll
        for (int k = 0; k < 8; ++k) s = fmaf(h[k], wv[lane + 32 * k], s);
#pragma unroll
        for (int off = 16; off; off >>= 1) s += __shfl_xor_sync(0xFFFFFFFFu, s, off);
        red[o] = s;
    }

    if (lane < 3) {
        int a = lane;
        int b = wid / HW;
        int pp = wid % HW;
        int yy = pp / W, xx = pp % W;

        float logit = red[a] + cls_b[a];
        float score = 1.f / (1.f + expf(-logit));

        float ddx = red[3 + 4 * a + 0] + reg_b[4 * a + 0];
        float ddy = red[3 + 4 * a + 1] + reg_b[4 * a + 1];
        float ddw = red[3 + 4 * a + 2] + reg_b[4 * a + 2];
        float ddh = red[3 + 4 * a + 3] + reg_b[4 * a + 3];

        float stride = (LEVEL == 0) ? 8.f : 16.f;
        float cx0 = (xx + 0.5f) * stride;
        float cy0 = (yy + 0.5f) * stride;
        float wsv = c_ws[LEVEL][a], hsv = c_hs[LEVEL][a];
        float ax1 = clamp256(cx0 - 0.5f * wsv);
        float ay1 = clamp256(cy0 - 0.5f * hsv);
        float ax2 = clamp256(cx0 + 0.5f * wsv);
        float ay2 = clamp256(cy0 + 0.5f * hsv);
        float wa = ax2 - ax1, ha = ay2 - ay1;
        float cxa = ax1 + 0.5f * wa, cya = ay1 + 0.5f * ha;

        float cx = ddx * wa + cxa;
        float cy = ddy * ha + cya;
        float ww = expf(ddw) * wa;
        float hh = expf(ddh) * ha;
        float bx1 = clamp256(cx - 0.5f * ww);
        float by1 = clamp256(cy - 0.5f * hh);
        float bx2 = clamp256(cx + 0.5f * ww);
        float by2 = clamp256(cy + 0.5f * hh);

        int ai = pp * 3 + a;
        if (LEVEL == 0) {
            g_boxes0[b * (HW * 3) + ai] = make_float4(bx1, by1, bx2, by2);
            g_scores0[b * (HW * 3) + ai] = score;
        } else {
            g_boxes1[b * (HW * 3) + ai] = make_float4(bx1, by1, bx2, by2);
            g_scores1[b * (HW * 3) + ai] = score;
        }
    }
}

// ---------------- per-task stable sort: register-resident bitonic ----------------
__global__ void __launch_bounds__(1024) sort_kernel()
{
    int task = blockIdx.x;
    int tid = threadIdx.x;
    int level = task >> 2, b = task & 3;
    int N = level ? 768 : 3072;
    const float* sc = level ? (g_scores1 + b * 768) : (g_scores0 + b * 3072);
    const float4* bx = level ? (g_boxes1 + b * 768) : (g_boxes0 + b * 3072);

    __shared__ unsigned long long sk[4096];

    unsigned long long v[4];
#pragma unroll
    for (int r = 0; r < 4; ++r) {
        int e = tid + (r << 10);
        v[r] = (e < N)
            ? ((((unsigned long long)__float_as_uint(sc[e])) << 32) |
               (unsigned long long)(0xFFFFFFFFu - (unsigned)e))
            : 0ull;
    }

    for (int k = 2; k <= 4096; k <<= 1) {
        for (int j = k >> 1; j > 0; j >>= 1) {
            if (j >= 1024) {
                int s = j >> 10;
#pragma unroll
                for (int r = 0; r < 4; ++r) {
                    int pr = r ^ s;
                    if (pr > r) {
                        int e = tid + (r << 10);
                        bool desc = ((e & k) == 0);
                        unsigned long long a = v[r], c = v[pr];
                        if (desc ? (a < c) : (a > c)) { v[r] = c; v[pr] = a; }
                    }
                }
            } else if (j >= 32) {
                __syncthreads();
#pragma unroll
                for (int r = 0; r < 4; ++r) sk[tid + (r << 10)] = v[r];
                __syncthreads();
#pragma unroll
                for (int r = 0; r < 4; ++r) {
                    int e = tid + (r << 10);
                    unsigned long long a = v[r];
                    unsigned long long c = sk[(tid ^ j) + (r << 10)];
                    bool desc = ((e & k) == 0);
                    bool left = ((tid & j) == 0);
                    bool take = left ? (desc ? (c > a) : (c < a))
                                     : (desc ? (c < a) : (c > a));
                    if (take) v[r] = c;
                }
            } else {
#pragma unroll
                for (int r = 0; r < 4; ++r) {
                    int e = tid + (r << 10);
                    unsigned long long a = v[r];
                    unsigned long long c = __shfl_xor_sync(0xFFFFFFFFu, a, j);
                    bool desc = ((e & k) == 0);
                    bool left = ((tid & j) == 0);
                    bool take = left ? (desc ? (c > a) : (c < a))
                                     : (desc ? (c < a) : (c > a));
                    if (take) v[r] = c;
                }
            }
        }
    }

#pragma unroll
    for (int r = 0; r < 4; ++r) {
        int e = tid + (r << 10);
        if (e < N) {
            unsigned long long kk = v[r];
            unsigned idx = 0xFFFFFFFFu - (unsigned)(kk & 0xFFFFFFFFu);
            g_sscores[task * 3072 + e] = __uint_as_float((unsigned)(kk >> 32));
            g_sboxes[task * 3072 + e] = bx[idx];
        }
    }
}

// ---------------- IoU suppression bitmask (division-free fast path) ----------------
__global__ void __launch_bounds__(256) mask_kernel()
{
    int task = blockIdx.y;
    int level = task >> 2;
    int N = level ? 768 : 3072;
    int words = level ? 24 : 96;
    int idx = blockIdx.x * blockDim.x + threadIdx.x;
    if (idx >= N * words) return;
    int w = idx / N;
    int i = idx % N;
    int j0 = w * 32;

    unsigned* dst = g_mask + (size_t)task * 3072u * 96u + (size_t)i * words + w;
    if (j0 + 31 <= i) { *dst = 0u; return; }   // scan only consumes j > i bits

    const float4* __restrict__ sb = g_sboxes + task * 3072;
    float4 bi = sb[i];
    float areai = (bi.z - bi.x) * (bi.w - bi.y);

    unsigned bits = 0, amb = 0;
#pragma unroll 4
    for (int jj = 0; jj < 32; ++jj) {
        float4 bj = __ldg(&sb[j0 + jj]);
        float xx1 = fmaxf(bi.x, bj.x), yy1 = fmaxf(bi.y, bj.y);
        float xx2 = fminf(bi.z, bj.z), yy2 = fminf(bi.w, bj.w);
        float iw = xx2 - xx1, ih = yy2 - yy1;
        float areaj = (bj.z - bj.x) * (bj.w - bj.y);
        float inter = iw * ih;
        float s = areai + areaj;
        float u = s - inter;
        float d = fmaf(0.7f, u, -inter);   // d < 0  <=>  iou > 0.7 (up to rounding)
        float m = 1e-4f * s;               // safety band >> all rounding error
        bool pos = (iw > 0.f) && (ih > 0.f);
        if (pos && (d < -m)) bits |= (1u << jj);
        if (pos && (fabsf(d) <= m)) amb |= (1u << jj);
    }
    while (amb) {
        int jj = __ffs(amb) - 1;
        amb &= amb - 1;
        float4 bj = __ldg(&sb[j0 + jj]);
        float xx1 = fmaxf(bi.x, bj.x), yy1 = fmaxf(bi.y, bj.y);
        float xx2 = fminf(bi.z, bj.z), yy2 = fminf(bi.w, bj.w);
        float iw = fmaxf(xx2 - xx1, 0.f), ih = fmaxf(yy2 - yy1, 0.f);
        float inter = iw * ih;
        float areaj = (bj.z - bj.x) * (bj.w - bj.y);
        float u = (areai + areaj) - inter;
        if (inter / u > 0.7f) bits |= (1u << jj);
        else                  bits &= ~(1u << jj);
    }
    *dst = bits;
}

// ---------------- greedy NMS scan v2: index-only critical path ----------------
// The greedy loop records kept INDICES into smem (STS, issue-only). The box/
// score gather happens in a parallel pass afterwards — no global-load latency
// on the per-kept dependence chain. Same greedy decisions; identical output.
__global__ void __launch_bounds__(128) nms_scan_kernel()
{
    int task = blockIdx.x;
    int level = task >> 2;
    const int words = level ? 24 : 96;
    const int wpg = 32 * words;
    const int u4pg = wpg / 4;

    float4* kb = g_kb + task * TOPK;
    float* ksc = g_ks + task * TOPK;
    int tid = threadIdx.x;
    int lane = tid & 31, wrp = tid >> 5;

    for (int s = tid; s < TOPK; s += 128) {
        kb[s] = make_float4(-1.f, -1.f, -1.f, -1.f);
        ksc[s] = -1.f;
    }

    __shared__ unsigned buf[2][32 * 96];
    __shared__ int s_idx[TOPK];
    __shared__ int s_stop, s_nkept;
    if (tid == 0) { s_stop = 0; s_nkept = 0; }

    const unsigned* __restrict__ mask = g_mask + (size_t)task * 3072u * 96u;

    {
        const uint4* src = (const uint4*)mask;
        uint4* dst = (uint4*)buf[0];
        for (int t = tid; t < u4pg; t += 128) dst[t] = src[t];
    }
    __syncthreads();

    int kept = 0;
    unsigned rem0 = 0, rem1 = 0, rem2 = 0;   // distributed removed mask (word s*32+lane)

    for (int g = 0; g < words; ++g) {
        if (wrp > 0 && g + 1 < words) {
            const uint4* src = (const uint4*)(mask + (size_t)(g + 1) * wpg);
            uint4* dst = (uint4*)buf[(g + 1) & 1];
            for (int t = tid - 32; t < u4pg; t += 96) dst[t] = src[t];
        }
        if (wrp == 0) {
            const unsigned* __restrict__ cb = buf[g & 1];
            int sel = g >> 5;
            unsigned start = (sel == 0) ? rem0 : ((sel == 1) ? rem1 : rem2);
            unsigned cur = __shfl_sync(0xFFFFFFFFu, start, g & 31);  // once per group
            unsigned avail = ~cur;
            while (avail) {
                int bit = __ffs(avail) - 1;
                if (lane == 0) s_idx[kept] = g * 32 + bit;   // STS: off the chain
                kept++;
                if (kept >= TOPK) { if (lane == 0) s_stop = 1; break; }
                const unsigned* __restrict__ row = cb + bit * words;
                cur |= row[g];                               // LDS broadcast: the chain
                if (lane < words)      rem0 |= row[lane];
                if (32 + lane < words) rem1 |= row[32 + lane];
                if (64 + lane < words) rem2 |= row[64 + lane];
                avail = ~cur & ((bit == 31) ? 0u : (0xFFFFFFFFu << (bit + 1)));
            }
        }
        __syncthreads();
        if (s_stop) break;
    }

    if (tid == 0) s_nkept = kept;
    __syncthreads();
    int nk = s_nkept;

    // parallel gather: MLP-overlapped global loads, no serial dependence
    const float4* __restrict__ sb = g_sboxes + task * 3072;
    const float* __restrict__ ss = g_sscores + task * 3072;
    for (int s = tid; s < nk; s += 128) {
        int i = s_idx[s];
        kb[s] = sb[i];
        ksc[s] = ss[i];
    }
}

// ---------------- per-image stable merge of the two levels ----------------
__global__ void __launch_bounds__(512) merge_kernel(float4* __restrict__ out)
{
    int b = blockIdx.x;
    int p = blockIdx.y * blockDim.x + threadIdx.x;
    if (p >= 2 * TOPK) return;
    const float* __restrict__ A = g_ks + b * TOPK;
    const float* __restrict__ B = g_ks + (4 + b) * TOPK;

    int lo = p > TOPK ? p - TOPK : 0;
    int hi = p < TOPK ? p : TOPK;
    while (lo < hi) {
        int i = (lo + hi) >> 1;
        int j = p - i;
        if (A[i] >= B[j - 1]) lo = i + 1;  // tie -> A first (stable)
        else hi = i;
    }
    int i = lo, j = p - i;
    bool takeA = (i < TOPK) && (j >= TOPK || A[i] >= B[j]);
    float4 v = takeA ? g_kb[b * TOPK + i] : g_kb[(4 + b) * TOPK + j];
    out[b * 2 * TOPK + p] = v;
}

// ---------------- launch ----------------
extern "C" void kernel_launch(void* const* d_in, const int* in_sizes, int n_in,
                              void* d_out, int out_size)
{
    const float* feat0  = (const float*)d_in[0];
    const float* feat1  = (const float*)d_in[1];
    const float* conv_w = (const float*)d_in[2];
    const float* conv_b = (const float*)d_in[3];
    const float* cls_w  = (const float*)d_in[4];
    const float* cls_b  = (const float*)d_in[5];
    const float* reg_w  = (const float*)d_in[6];
    const float* reg_b  = (const float*)d_in[7];
    (void)in_sizes; (void)n_in; (void)out_size;

    wtrans_kernel<<<(C_CH * C_CH * 9 + 255) / 256, 256>>>(conv_w);            // 1

    conv3x3_kernel<16, 16, 1><<<dim3(8, 4, 3), 128>>>(feat1);                 // 2
    heads_kernel<16, 16, 1><<<128, 256>>>(conv_b, cls_w, cls_b, reg_w, reg_b);// 3

    conv3x3_kernel<32, 32, 0><<<dim3(32, 4, 3), 128>>>(feat0);                // 4 (profiled)
    heads_kernel<32, 32, 0><<<512, 256>>>(conv_b, cls_w, cls_b, reg_w, reg_b);// 5

    sort_kernel<<<8, 1024>>>();                                               // 6

    mask_kernel<<<dim3((96 * 3072 + 255) / 256, 8), 256>>>();                 // 7

    nms_scan_kernel<<<8, 128>>>();                                            // 8

    merge_kernel<<<dim3(4, 4), 512>>>((float4*)d_out);                        // 9
}

// round 14
// speedup vs baseline: 2.4367x; 1.0657x over previous
#include <cuda_runtime.h>
#include <cuda_bf16.h>
#include <math.h>
#include <stdint.h>

// ---------------- problem constants ----------------
#define C_CH   256
#define TOPK   1000

__device__ __constant__ float c_ws[2][3] = {
    {90.50966799187809f, 64.0f, 45.254833995939045f},
    {181.01933598375618f, 128.0f, 90.50966799187809f}};
__device__ __constant__ float c_hs[2][3] = {
    {45.254833995939045f, 64.0f, 90.50966799187809f},
    {90.50966799187809f, 128.0f, 181.01933598375618f}};

// ---------------- device scratch (static, no allocs) ----------------
__device__ float  g_part0[9 * 4096 * C_CH];      // level0 conv partials (per tap)
__device__ float  g_part1[9 * 1024 * C_CH];      // level1 conv partials (per tap)
__device__ float  g_wt[9 * C_CH * C_CH];         // transposed conv weights [tap][ci][co]
__device__ float4 g_boxes0[4 * 3072];
__device__ float4 g_boxes1[4 * 768];
__device__ float  g_scores0[4 * 3072];
__device__ float  g_scores1[4 * 768];
__device__ float4 g_sboxes[8 * 3072];            // per-task sorted boxes
__device__ float  g_sscores[8 * 3072];           // per-task sorted scores
__device__ unsigned g_mask[8u * 3072u * 96u];    // IoU>thresh bitmask, row-major per task
__device__ float4 g_kb[8 * TOPK];                // kept boxes per task
__device__ float  g_ks[8 * TOPK];                // kept scores per task

// ---------------- small PTX helpers ----------------
__device__ __forceinline__ void fma2(unsigned long long& d, unsigned long long a,
                                     unsigned long long b)
{
    asm("fma.rn.f32x2 %0, %1, %2, %0;" : "+l"(d) : "l"(a), "l"(b));
}
__device__ __forceinline__ unsigned long long pack_dup(float v)
{
    unsigned long long r;
    unsigned u = __float_as_uint(v);
    asm("mov.b64 %0, {%1, %1};" : "=l"(r) : "r"(u));
    return r;
}
__device__ __forceinline__ void cp_async16(uint32_t dst, const void* src)
{
    asm volatile("cp.async.cg.shared.global [%0], [%1], 16;" :: "r"(dst), "l"(src));
}
__device__ __forceinline__ void cp_async4(uint32_t dst, const void* src, bool ok)
{
    int sz = ok ? 4 : 0;
    asm volatile("cp.async.ca.shared.global [%0], [%1], 4, %2;" :: "r"(dst), "l"(src), "r"(sz));
}

// ---------------- weight transpose ----------------
__global__ void wtrans_kernel(const float* __restrict__ w)
{
    int idx = blockIdx.x * blockDim.x + threadIdx.x;
    if (idx >= C_CH * C_CH * 9) return;
    int co  = idx / (C_CH * 9);
    int r   = idx % (C_CH * 9);
    int ci  = r / 9;
    int tap = r % 9;
    g_wt[(tap * C_CH + ci) * C_CH + co] = w[idx];
}

// ---------------- 3x3 conv, split-K per TAP (z=9), f32x2 packed FMA ----------------
// 64co x 128pos tile, 128 threads, 8co x 8pos per thread. Same inner loop as the
// 111us round-8 kernel; only the K-split granularity changed (3 taps -> 1 tap
// per block) so the grid triples and all 4 blocks/SM slots fill.
template <int H, int W, int LEVEL>
__global__ void __launch_bounds__(128, 4) conv3x3_kernel(const float* __restrict__ xin)
{
    constexpr int HW = H * W;
    constexpr int NSLICE = 16;   // one tap, 16-deep ci slices
    float* __restrict__ outp = ((LEVEL == 0) ? g_part0 : g_part1)
                               + (size_t)blockIdx.z * (4 * HW * C_CH);

    const int tid  = threadIdx.x;
    const int n0   = blockIdx.x * 128;  // 128 | HW, never crosses image
    const int co0  = blockIdx.y * 64;
    const int b    = n0 / HW;
    const int p0   = n0 % HW;
    const int cth  = tid & 7;           // 8 co-groups of 8
    const int pth  = tid >> 3;          // 16 pos-groups of 8
    const int tap  = blockIdx.z;
    const float* __restrict__ xb = xin + (size_t)b * C_CH * HW;

    __shared__ float As[3][16][64];
    __shared__ float Bs[3][16][128];
    uint32_t sA = (uint32_t)__cvta_generic_to_shared(&As[0][0][0]);
    uint32_t sB = (uint32_t)__cvta_generic_to_shared(&Bs[0][0][0]);

    const int p  = p0 + tid;
    const int py = p / W, px = p % W;
    const int dy = tap / 3 - 1, dx = tap % 3 - 1;
    const int ys = py + dy, xs = px + dx;
    const bool ok = ((unsigned)ys < (unsigned)H) && ((unsigned)xs < (unsigned)W);
    const float* __restrict__ wtap = g_wt + (size_t)tap * C_CH * C_CH + co0;
    const float* __restrict__ bcol = xb + (ys * W + xs);

    unsigned long long acc[8][4];
#pragma unroll
    for (int i = 0; i < 8; ++i)
#pragma unroll
        for (int j = 0; j < 4; ++j) acc[i][j] = 0ull;

#define ISSUE_SLICE(s)                                                           \
    {                                                                            \
        int buf = (s) % 3;                                                       \
        int ci0 = (s) << 4;                                                      \
        const float* wbase = wtap + (size_t)ci0 * C_CH;                          \
        _Pragma("unroll")                                                        \
        for (int r = 0; r < 2; ++r) {                                            \
            int f4 = tid + 128 * r;                                              \
            int kk = f4 >> 4, c4 = f4 & 15;                                      \
            cp_async16(sA + buf * (16*64*4) + (kk * 64 + c4 * 4) * 4,            \
                       wbase + (size_t)kk * C_CH + c4 * 4);                      \
        }                                                                        \
        const float* bsrc = bcol + (size_t)ci0 * HW;                             \
        _Pragma("unroll")                                                        \
        for (int r = 0; r < 16; ++r)                                             \
            cp_async4(sB + buf * (16*128*4) + (r * 128 + tid) * 4,               \
                      bsrc + (size_t)r * HW, ok);                                \
        asm volatile("cp.async.commit_group;");                                  \
    }

    ISSUE_SLICE(0);
    ISSUE_SLICE(1);

    for (int s = 0; s < NSLICE; ++s) {
        if (s + 2 < NSLICE) {
            asm volatile("cp.async.wait_group 1;");   // slice s arrived
            __syncthreads();                          // publish s; frees buf (s-1)%3
            ISSUE_SLICE(s + 2);                       // writes buf (s+2)%3 == (s-1)%3
        } else {
            asm volatile("cp.async.wait_group %0;" :: "n"(0) : "memory");
            __syncthreads();
        }
        const float (*Ab)[64]  = As[s % 3];
        const float (*Bb)[128] = Bs[s % 3];
#pragma unroll
        for (int kk = 0; kk < 16; ++kk) {
            float4 a0 = *(const float4*)&Ab[kk][cth * 8];
            float4 a1 = *(const float4*)&Ab[kk][cth * 8 + 4];
            ulonglong2 bl0 = *(const ulonglong2*)&Bb[kk][pth * 8];
            ulonglong2 bl1 = *(const ulonglong2*)&Bb[kk][pth * 8 + 4];
            unsigned long long bb[4] = {bl0.x, bl0.y, bl1.x, bl1.y};
            float av[8] = {a0.x, a0.y, a0.z, a0.w, a1.x, a1.y, a1.z, a1.w};
#pragma unroll
            for (int i = 0; i < 8; ++i) {
                unsigned long long ad = pack_dup(av[i]);
#pragma unroll
                for (int j = 0; j < 4; ++j) fma2(acc[i][j], ad, bb[j]);
            }
        }
    }
#undef ISSUE_SLICE

#pragma unroll
    for (int j = 0; j < 4; ++j)
#pragma unroll
        for (int h = 0; h < 2; ++h) {
            int n = n0 + pth * 8 + j * 2 + h;
            float v[8];
#pragma unroll
            for (int i = 0; i < 8; ++i) {
                float2 f = *reinterpret_cast<float2*>(&acc[i][j]);
                v[i] = h ? f.y : f.x;
            }
            *(float4*)&outp[(size_t)n * C_CH + co0 + cth * 8] =
                make_float4(v[0], v[1], v[2], v[3]);
            *(float4*)&outp[(size_t)n * C_CH + co0 + cth * 8 + 4] =
                make_float4(v[4], v[5], v[6], v[7]);
        }
}

// ---------------- heads: combine 9 partials + bias + relu, 1x1 heads, decode ----------------
__device__ __forceinline__ float clamp256(float v)
{
    return fminf(fmaxf(v, 0.f), 256.f);
}

template <int H, int W, int LEVEL>
__global__ void __launch_bounds__(256) heads_kernel(const float* __restrict__ conv_b,
                                                    const float* __restrict__ cls_w,
                                                    const float* __restrict__ cls_b,
                                                    const float* __restrict__ reg_w,
                                                    const float* __restrict__ reg_b)
{
    constexpr int HW = H * W;
    constexpr int NPOS = 4 * HW;
    const float* __restrict__ part = (LEVEL == 0) ? g_part0 : g_part1;

    int wid  = (blockIdx.x * blockDim.x + threadIdx.x) >> 5;
    int lane = threadIdx.x & 31;
    if (wid >= NPOS) return;

    const float* __restrict__ base = part + (size_t)wid * C_CH;
    float h[8];
#pragma unroll
    for (int k = 0; k < 8; ++k) {
        int c = lane + 32 * k;
        float v = base[c];
#pragma unroll
        for (int t = 1; t < 9; ++t) v += base[(size_t)t * NPOS * C_CH + c];
        v += conv_b[c];
        h[k] = v > 0.f ? v : 0.f;
    }

    float red[15];
#pragma unroll
    for (int o = 0; o < 15; ++o) {
        const float* __restrict__ wv = (o < 3) ? (cls_w + o * C_CH) : (reg_w + (o - 3) * C_CH);
        float s = 0.f;
#pragma unroll
        for (int k = 0; k < 8; ++k) s = fmaf(h[k], wv[lane + 32 * k], s);
#pragma unroll
        for (int off = 16; off; off >>= 1) s += __shfl_xor_sync(0xFFFFFFFFu, s, off);
        red[o] = s;
    }

    if (lane < 3) {
        int a = lane;
        int b = wid / HW;
        int pp = wid % HW;
        int yy = pp / W, xx = pp % W;

        float logit = red[a] + cls_b[a];
        float score = 1.f / (1.f + expf(-logit));

        float ddx = red[3 + 4 * a + 0] + reg_b[4 * a + 0];
        float ddy = red[3 + 4 * a + 1] + reg_b[4 * a + 1];
        float ddw = red[3 + 4 * a + 2] + reg_b[4 * a + 2];
        float ddh = red[3 + 4 * a + 3] + reg_b[4 * a + 3];

        float stride = (LEVEL == 0) ? 8.f : 16.f;
        float cx0 = (xx + 0.5f) * stride;
        float cy0 = (yy + 0.5f) * stride;
        float wsv = c_ws[LEVEL][a], hsv = c_hs[LEVEL][a];
        float ax1 = clamp256(cx0 - 0.5f * wsv);
        float ay1 = clamp256(cy0 - 0.5f * hsv);
        float ax2 = clamp256(cx0 + 0.5f * wsv);
        float ay2 = clamp256(cy0 + 0.5f * hsv);
        float wa = ax2 - ax1, ha = ay2 - ay1;
        float cxa = ax1 + 0.5f * wa, cya = ay1 + 0.5f * ha;

        float cx = ddx * wa + cxa;
        float cy = ddy * ha + cya;
        float ww = expf(ddw) * wa;
        float hh = expf(ddh) * ha;
        float bx1 = clamp256(cx - 0.5f * ww);
        float by1 = clamp256(cy - 0.5f * hh);
        float bx2 = clamp256(cx + 0.5f * ww);
        float by2 = clamp256(cy + 0.5f * hh);

        int ai = pp * 3 + a;
        if (LEVEL == 0) {
            g_boxes0[b * (HW * 3) + ai] = make_float4(bx1, by1, bx2, by2);
            g_scores0[b * (HW * 3) + ai] = score;
        } else {
            g_boxes1[b * (HW * 3) + ai] = make_float4(bx1, by1, bx2, by2);
            g_scores1[b * (HW * 3) + ai] = score;
        }
    }
}

// ---------------- per-task stable sort: register-resident bitonic ----------------
__global__ void __launch_bounds__(1024) sort_kernel()
{
    int task = blockIdx.x;
    int tid = threadIdx.x;
    int level = task >> 2, b = task & 3;
    int N = level ? 768 : 3072;
    const float* sc = level ? (g_scores1 + b * 768) : (g_scores0 + b * 3072);
    const float4* bx = level ? (g_boxes1 + b * 768) : (g_boxes0 + b * 3072);

    __shared__ unsigned long long sk[4096];

    unsigned long long v[4];
#pragma unroll
    for (int r = 0; r < 4; ++r) {
        int e = tid + (r << 10);
        v[r] = (e < N)
            ? ((((unsigned long long)__float_as_uint(sc[e])) << 32) |
               (unsigned long long)(0xFFFFFFFFu - (unsigned)e))
            : 0ull;
    }

    for (int k = 2; k <= 4096; k <<= 1) {
        for (int j = k >> 1; j > 0; j >>= 1) {
            if (j >= 1024) {
                int s = j >> 10;
#pragma unroll
                for (int r = 0; r < 4; ++r) {
                    int pr = r ^ s;
                    if (pr > r) {
                        int e = tid + (r << 10);
                        bool desc = ((e & k) == 0);
                        unsigned long long a = v[r], c = v[pr];
                        if (desc ? (a < c) : (a > c)) { v[r] = c; v[pr] = a; }
                    }
                }
            } else if (j >= 32) {
                __syncthreads();
#pragma unroll
                for (int r = 0; r < 4; ++r) sk[tid + (r << 10)] = v[r];
                __syncthreads();
#pragma unroll
                for (int r = 0; r < 4; ++r) {
                    int e = tid + (r << 10);
                    unsigned long long a = v[r];
                    unsigned long long c = sk[(tid ^ j) + (r << 10)];
                    bool desc = ((e & k) == 0);
                    bool left = ((tid & j) == 0);
                    bool take = left ? (desc ? (c > a) : (c < a))
                                     : (desc ? (c < a) : (c > a));
                    if (take) v[r] = c;
                }
            } else {
#pragma unroll
                for (int r = 0; r < 4; ++r) {
                    int e = tid + (r << 10);
                    unsigned long long a = v[r];
                    unsigned long long c = __shfl_xor_sync(0xFFFFFFFFu, a, j);
                    bool desc = ((e & k) == 0);
                    bool left = ((tid & j) == 0);
                    bool take = left ? (desc ? (c > a) : (c < a))
                                     : (desc ? (c < a) : (c > a));
                    if (take) v[r] = c;
                }
            }
        }
    }

#pragma unroll
    for (int r = 0; r < 4; ++r) {
        int e = tid + (r << 10);
        if (e < N) {
            unsigned long long kk = v[r];
            unsigned idx = 0xFFFFFFFFu - (unsigned)(kk & 0xFFFFFFFFu);
            g_sscores[task * 3072 + e] = __uint_as_float((unsigned)(kk >> 32));
            g_sboxes[task * 3072 + e] = bx[idx];
        }
    }
}

// ---------------- IoU suppression bitmask (division-free fast path) ----------------
__global__ void __launch_bounds__(256) mask_kernel()
{
    int task = blockIdx.y;
    int level = task >> 2;
    int N = level ? 768 : 3072;
    int words = level ? 24 : 96;
    int idx = blockIdx.x * blockDim.x + threadIdx.x;
    if (idx >= N * words) return;
    int w = idx / N;
    int i = idx % N;
    int j0 = w * 32;

    unsigned* dst = g_mask + (size_t)task * 3072u * 96u + (size_t)i * words + w;
    if (j0 + 31 <= i) { *dst = 0u; return; }   // scan only consumes j > i bits

    const float4* __restrict__ sb = g_sboxes + task * 3072;
    float4 bi = sb[i];
    float areai = (bi.z - bi.x) * (bi.w - bi.y);

    unsigned bits = 0, amb = 0;
#pragma unroll 4
    for (int jj = 0; jj < 32; ++jj) {
        float4 bj = __ldg(&sb[j0 + jj]);
        float xx1 = fmaxf(bi.x, bj.x), yy1 = fmaxf(bi.y, bj.y);
        float xx2 = fminf(bi.z, bj.z), yy2 = fminf(bi.w, bj.w);
        float iw = xx2 - xx1, ih = yy2 - yy1;
        float areaj = (bj.z - bj.x) * (bj.w - bj.y);
        float inter = iw * ih;
        float s = areai + areaj;
        float u = s - inter;
        float d = fmaf(0.7f, u, -inter);   // d < 0  <=>  iou > 0.7 (up to rounding)
        float m = 1e-4f * s;               // safety band >> all rounding error
        bool pos = (iw > 0.f) && (ih > 0.f);
        if (pos && (d < -m)) bits |= (1u << jj);
        if (pos && (fabsf(d) <= m)) amb |= (1u << jj);
    }
    while (amb) {
        int jj = __ffs(amb) - 1;
        amb &= amb - 1;
        float4 bj = __ldg(&sb[j0 + jj]);
        float xx1 = fmaxf(bi.x, bj.x), yy1 = fmaxf(bi.y, bj.y);
        float xx2 = fminf(bi.z, bj.z), yy2 = fminf(bi.w, bj.w);
        float iw = fmaxf(xx2 - xx1, 0.f), ih = fmaxf(yy2 - yy1, 0.f);
        float inter = iw * ih;
        float areaj = (bj.z - bj.x) * (bj.w - bj.y);
        float u = (areai + areaj) - inter;
        if (inter / u > 0.7f) bits |= (1u << jj);
        else                  bits &= ~(1u << jj);
    }
    *dst = bits;
}

// ---------------- greedy NMS scan v2: index-only critical path ----------------
__global__ void __launch_bounds__(128) nms_scan_kernel()
{
    int task = blockIdx.x;
    int level = task >> 2;
    const int words = level ? 24 : 96;
    const int wpg = 32 * words;
    const int u4pg = wpg / 4;

    float4* kb = g_kb + task * TOPK;
    float* ksc = g_ks + task * TOPK;
    int tid = threadIdx.x;
    int lane = tid & 31, wrp = tid >> 5;

    for (int s = tid; s < TOPK; s += 128) {
        kb[s] = make_float4(-1.f, -1.f, -1.f, -1.f);
        ksc[s] = -1.f;
    }

    __shared__ unsigned buf[2][32 * 96];
    __shared__ int s_idx[TOPK];
    __shared__ int s_stop, s_nkept;
    if (tid == 0) { s_stop = 0; s_nkept = 0; }

    const unsigned* __restrict__ mask = g_mask + (size_t)task * 3072u * 96u;

    {
        const uint4* src = (const uint4*)mask;
        uint4* dst = (uint4*)buf[0];
        for (int t = tid; t < u4pg; t += 128) dst[t] = src[t];
    }
    __syncthreads();

    int kept = 0;
    unsigned rem0 = 0, rem1 = 0, rem2 = 0;   // distributed removed mask (word s*32+lane)

    for (int g = 0; g < words; ++g) {
        if (wrp > 0 && g + 1 < words) {
            const uint4* src = (const uint4*)(mask + (size_t)(g + 1) * wpg);
            uint4* dst = (uint4*)buf[(g + 1) & 1];
            for (int t = tid - 32; t < u4pg; t += 96) dst[t] = src[t];
        }
        if (wrp == 0) {
            const unsigned* __restrict__ cb = buf[g & 1];
            int sel = g >> 5;
            unsigned start = (sel == 0) ? rem0 : ((sel == 1) ? rem1 : rem2);
            unsigned cur = __shfl_sync(0xFFFFFFFFu, start, g & 31);  // once per group
            unsigned avail = ~cur;
            while (avail) {
                int bit = __ffs(avail) - 1;
                if (lane == 0) s_idx[kept] = g * 32 + bit;   // STS: off the chain
                kept++;
                if (kept >= TOPK) { if (lane == 0) s_stop = 1; break; }
                const unsigned* __restrict__ row = cb + bit * words;
                cur |= row[g];                               // LDS broadcast: the chain
                if (lane < words)      rem0 |= row[lane];
                if (32 + lane < words) rem1 |= row[32 + lane];
                if (64 + lane < words) rem2 |= row[64 + lane];
                avail = ~cur & ((bit == 31) ? 0u : (0xFFFFFFFFu << (bit + 1)));
            }
        }
        __syncthreads();
        if (s_stop) break;
    }

    if (tid == 0) s_nkept = kept;
    __syncthreads();
    int nk = s_nkept;

    // parallel gather: MLP-overlapped global loads, no serial dependence
    const float4* __restrict__ sb = g_sboxes + task * 3072;
    const float* __restrict__ ss = g_sscores + task * 3072;
    for (int s = tid; s < nk; s += 128) {
        int i = s_idx[s];
        kb[s] = sb[i];
        ksc[s] = ss[i];
    }
}

// ---------------- per-image stable merge of the two levels ----------------
__global__ void __launch_bounds__(512) merge_kernel(float4* __restrict__ out)
{
    int b = blockIdx.x;
    int p = blockIdx.y * blockDim.x + threadIdx.x;
    if (p >= 2 * TOPK) return;
    const float* __restrict__ A = g_ks + b * TOPK;
    const float* __restrict__ B = g_ks + (4 + b) * TOPK;

    int lo = p > TOPK ? p - TOPK : 0;
    int hi = p < TOPK ? p : TOPK;
    while (lo < hi) {
        int i = (lo + hi) >> 1;
        int j = p - i;
        if (A[i] >= B[j - 1]) lo = i + 1;  // tie -> A first (stable)
        else hi = i;
    }
    int i = lo, j = p - i;
    bool takeA = (i < TOPK) && (j >= TOPK || A[i] >= B[j]);
    float4 v = takeA ? g_kb[b * TOPK + i] : g_kb[(4 + b) * TOPK + j];
    out[b * 2 * TOPK + p] = v;
}

// ---------------- launch ----------------
extern "C" void kernel_launch(void* const* d_in, const int* in_sizes, int n_in,
                              void* d_out, int out_size)
{
    const float* feat0  = (const float*)d_in[0];
    const float* feat1  = (const float*)d_in[1];
    const float* conv_w = (const float*)d_in[2];
    const float* conv_b = (const float*)d_in[3];
    const float* cls_w  = (const float*)d_in[4];
    const float* cls_b  = (const float*)d_in[5];
    const float* reg_w  = (const float*)d_in[6];
    const float* reg_b  = (const float*)d_in[7];
    (void)in_sizes; (void)n_in; (void)out_size;

    wtrans_kernel<<<(C_CH * C_CH * 9 + 255) / 256, 256>>>(conv_w);            // 1

    conv3x3_kernel<16, 16, 1><<<dim3(8, 4, 9), 128>>>(feat1);                 // 2
    heads_kernel<16, 16, 1><<<128, 256>>>(conv_b, cls_w, cls_b, reg_w, reg_b);// 3

    conv3x3_kernel<32, 32, 0><<<dim3(32, 4, 9), 128>>>(feat0);                // 4 (profiled)
    heads_kernel<32, 32, 0><<<512, 256>>>(conv_b, cls_w, cls_b, reg_w, reg_b);// 5

    sort_kernel<<<8, 1024>>>();                                               // 6

    mask_kernel<<<dim3((96 * 3072 + 255) / 256, 8), 256>>>();                 // 7

    nms_scan_kernel<<<8, 128>>>();                                            // 8

    merge_kernel<<<dim3(4, 4), 512>>>((float4*)d_out);                        // 9
}